// round 1
// baseline (speedup 1.0000x reference)
#include <cuda_runtime.h>
#include <cstdint>

#define C_MAX   256
#define N_MAX   65536
#define D_MAXEL 4096
#define BETA    0.3f
#define PA_ROWS 128

// -------- device scratch (static: no allocations allowed) --------
__device__ float g_sums[(size_t)C_MAX * D_MAXEL]; // class sums -> centroids (in place)
__device__ int   g_counts[C_MAX];
__device__ int   g_fill[C_MAX];
__device__ int   g_off[C_MAX + 1];
__device__ int   g_idx[N_MAX];    // sample index sorted by class
__device__ int   g_slab[N_MAX];   // label at sorted position
__device__ float g_d[N_MAX];      // per-sample squared distance
__device__ float g_loss;
__device__ int   g_npres;
__device__ int   g_is64;          // labels are int64?
__device__ int   g_C;

__device__ __forceinline__ int get_label(const void* labels, int i, int is64) {
    if (is64) return (int)((const long long*)labels)[i];
    return ((const int*)labels)[i];
}

__device__ __forceinline__ float blockReduceSum(float v) {
    __shared__ float sm[32];
    int lane = threadIdx.x & 31, w = threadIdx.x >> 5;
    #pragma unroll
    for (int o = 16; o; o >>= 1) v += __shfl_down_sync(0xffffffffu, v, o);
    if (lane == 0) sm[w] = v;
    __syncthreads();
    int nw = (blockDim.x + 31) >> 5;
    v = (threadIdx.x < nw) ? sm[threadIdx.x] : 0.f;
    if (w == 0) {
        #pragma unroll
        for (int o = 16; o; o >>= 1) v += __shfl_down_sync(0xffffffffu, v, o);
    }
    __syncthreads();
    return v; // valid in thread 0
}

// -------- kernels --------

__global__ void k_zero(int total_sums) {
    int idx = blockIdx.x * blockDim.x + threadIdx.x;
    if (idx < total_sums) g_sums[idx] = 0.f;
    if (idx < C_MAX) { g_counts[idx] = 0; g_fill[idx] = 0; }
    if (idx == 0) { g_loss = 0.f; g_npres = 0; }
}

// Detect label dtype (int32 vs int64 little-endian) + read num_classes.
__global__ void k_detect(const void* labels, const void* ncls, int N) {
    __shared__ int ok;
    if (threadIdx.x == 0) ok = 1;
    __syncthreads();
    const int* w = (const int*)labels;
    int bad = 0;
    for (int i = threadIdx.x; i < N / 2; i += blockDim.x)
        if (w[2 * i + 1] != 0) bad = 1;   // int32 labels: odd words are labels (nonzero w.h.p.)
    if (bad) ok = 0;
    __syncthreads();
    if (threadIdx.x == 0) {
        g_is64 = ok;
        int c = 100;
        if (ncls) c = ((const int*)ncls)[0]; // low 32 bits valid for int32 or LE int64
        if (c < 1 || c > C_MAX) c = 100;
        g_C = c;
    }
}

__global__ void k_hist(const void* labels, int N) {
    __shared__ int h[C_MAX];
    for (int i = threadIdx.x; i < C_MAX; i += blockDim.x) h[i] = 0;
    __syncthreads();
    int is64 = g_is64;
    for (int i = blockIdx.x * blockDim.x + threadIdx.x; i < N; i += gridDim.x * blockDim.x) {
        int l = get_label(labels, i, is64);
        atomicAdd(&h[l], 1);
    }
    __syncthreads();
    for (int i = threadIdx.x; i < C_MAX; i += blockDim.x)
        if (h[i]) atomicAdd(&g_counts[i], h[i]);
}

__global__ void k_scan() {
    // single thread: C_MAX <= 256, trivial
    int run = 0;
    for (int c = 0; c < C_MAX; c++) {
        g_off[c] = run;
        g_fill[c] = run;
        run += g_counts[c];
    }
    g_off[C_MAX] = run;
}

__global__ void k_scatter(const void* labels, int N) {
    __shared__ int lab[256];
    __shared__ int base[C_MAX];
    __shared__ int cnt1[C_MAX];
    __shared__ int cnt2[C_MAX];
    for (int i = threadIdx.x; i < C_MAX; i += blockDim.x) { cnt1[i] = 0; cnt2[i] = 0; }
    __syncthreads();
    int is64 = g_is64;
    int i = blockIdx.x * blockDim.x + threadIdx.x;
    int l = -1;
    if (i < N) {
        l = get_label(labels, i, is64);
        lab[threadIdx.x] = l;
        atomicAdd(&cnt1[l], 1);
    }
    __syncthreads();
    for (int c = threadIdx.x; c < C_MAX; c += blockDim.x)
        if (cnt1[c]) base[c] = atomicAdd(&g_fill[c], cnt1[c]);
    __syncthreads();
    if (i < N) {
        int r = atomicAdd(&cnt2[l], 1);
        int pos = base[l] + r;
        g_idx[pos] = i;
        g_slab[pos] = l;
    }
}

// Pass A: class sums over class-sorted rows. One column per thread,
// register accumulation across a run of same-class rows, flush on change.
__global__ void k_sums(const float* __restrict__ emb, int N, int D) {
    int col = blockIdx.y * blockDim.x + threadIdx.x;
    if (col >= D) return;
    int p0 = blockIdx.x * PA_ROWS;
    int p1 = min(p0 + PA_ROWS, N);
    int cur = -1;
    float acc = 0.f;
    for (int p = p0; p < p1; p++) {
        int c = g_slab[p];
        if (c != cur) {
            if (cur >= 0) atomicAdd(&g_sums[(size_t)cur * D + col], acc);
            cur = c; acc = 0.f;
        }
        long long i = g_idx[p];
        acc += emb[i * (long long)D + col];
    }
    if (cur >= 0) atomicAdd(&g_sums[(size_t)cur * D + col], acc);
}

__global__ void k_centroid(int D) {
    int idx = blockIdx.x * blockDim.x + threadIdx.x;
    int C = g_C;
    if (idx >= C * D) return;
    int c = idx / D;
    int cnt = g_counts[c];
    float inv = 1.f / (float)max(cnt, 1);
    g_sums[idx] *= inv;
}

// Pass B: per-sample squared distance to its class centroid.
__global__ void k_dist(const float* __restrict__ emb, const void* labels, int D) {
    int i = blockIdx.x;
    int is64 = g_is64;
    int l = get_label(labels, i, is64);
    const float* e = emb + (size_t)i * D;
    const float* c = g_sums + (size_t)l * D;
    float s = 0.f;
    for (int k = threadIdx.x; k < D; k += blockDim.x) {
        float df = e[k] - c[k];
        s = fmaf(df, df, s);
    }
    s = blockReduceSum(s);
    if (threadIdx.x == 0) g_d[i] = s;
}

// Per-class unbiased variance of d, accumulated into g_loss; count present classes.
__global__ void k_classvar() {
    int c = blockIdx.x;
    if (c >= g_C) return;
    int cnt = g_counts[c];
    if (cnt == 0) return;
    if (threadIdx.x == 0) atomicAdd(&g_npres, 1);
    if (cnt < 2) return;
    int o = g_off[c];
    __shared__ float sh_mean;
    float s = 0.f;
    for (int p = o + threadIdx.x; p < o + cnt; p += blockDim.x) s += g_d[g_idx[p]];
    s = blockReduceSum(s);
    if (threadIdx.x == 0) sh_mean = s / (float)cnt;
    __syncthreads();
    float mean = sh_mean;
    float v = 0.f;
    for (int p = o + threadIdx.x; p < o + cnt; p += blockDim.x) {
        float dv = g_d[g_idx[p]] - mean;
        v = fmaf(dv, dv, v);
    }
    v = blockReduceSum(v);
    if (threadIdx.x == 0) atomicAdd(&g_loss, v / (float)(cnt - 1));
}

__global__ void k_final(float* out) {
    float np = (float)max(g_npres, 1);
    out[0] = BETA * g_loss / np;
}

// -------- launch --------
extern "C" void kernel_launch(void* const* d_in, const int* in_sizes, int n_in,
                              void* d_out, int out_size) {
    const float* emb = (const float*)d_in[0];
    const void*  lab = d_in[1];
    const void*  ncl = (n_in >= 3) ? d_in[2] : nullptr;
    float* out = (float*)d_out;

    int N = in_sizes[1];
    int D = in_sizes[0] / N;
    int total_sums = C_MAX * D;

    k_zero<<<(total_sums + 255) / 256, 256>>>(total_sums);
    k_detect<<<1, 256>>>(lab, ncl, N);

    int hist_blocks = min(128, (N + 255) / 256);
    k_hist<<<hist_blocks, 256>>>(lab, N);
    k_scan<<<1, 1>>>();
    k_scatter<<<(N + 255) / 256, 256>>>(lab, N);

    dim3 gA((N + PA_ROWS - 1) / PA_ROWS, (D + 255) / 256);
    k_sums<<<gA, 256>>>(emb, N, D);
    k_centroid<<<(total_sums + 255) / 256, 256>>>(D);

    k_dist<<<N, 256>>>(emb, lab, D);
    k_classvar<<<C_MAX, 256>>>();
    k_final<<<1, 1>>>(out);
}

// round 2
// speedup vs baseline: 2.0102x; 2.0102x over previous
#include <cuda_runtime.h>
#include <cstdint>

#define C_MAX   256
#define N_MAX   65536
#define D_MAXEL 4096
#define BETA    0.3f
#define PA_ROWS 64

// -------- device scratch (static: no allocations allowed) --------
__device__ float g_sums[(size_t)C_MAX * D_MAXEL]; // class sums -> centroids (in place)
__device__ int   g_counts[C_MAX];
__device__ int   g_fill[C_MAX];
__device__ int   g_off[C_MAX + 1];
__device__ int   g_idx[N_MAX];    // sample index sorted by class
__device__ int   g_slab[N_MAX];   // label at sorted position
__device__ float g_d[N_MAX];      // per-sample squared distance
__device__ float g_loss;
__device__ int   g_npres;
__device__ int   g_is64;          // labels are int64?
__device__ int   g_C;

__device__ __forceinline__ int get_label(const void* labels, int i, int is64) {
    if (is64) return (int)((const long long*)labels)[i];
    return ((const int*)labels)[i];
}

__device__ __forceinline__ float blockReduceSum(float v) {
    __shared__ float sm[32];
    int lane = threadIdx.x & 31, w = threadIdx.x >> 5;
    #pragma unroll
    for (int o = 16; o; o >>= 1) v += __shfl_down_sync(0xffffffffu, v, o);
    if (lane == 0) sm[w] = v;
    __syncthreads();
    int nw = (blockDim.x + 31) >> 5;
    v = (threadIdx.x < nw) ? sm[threadIdx.x] : 0.f;
    if (w == 0) {
        #pragma unroll
        for (int o = 16; o; o >>= 1) v += __shfl_down_sync(0xffffffffu, v, o);
    }
    __syncthreads();
    return v; // valid in thread 0
}

// -------- kernels --------

__global__ void k_zero(int total4) {
    int idx = blockIdx.x * blockDim.x + threadIdx.x;
    if (idx < total4) ((float4*)g_sums)[idx] = make_float4(0.f, 0.f, 0.f, 0.f);
    if (idx < C_MAX) { g_counts[idx] = 0; g_fill[idx] = 0; }
    if (idx == 0) { g_loss = 0.f; g_npres = 0; }
}

// Detect label dtype (int32 vs int64 little-endian) + read num_classes.
// Sampling 2048 odd 32-bit words is conclusive: if labels were int32, odd
// words are labels themselves (uniform in [0,C)); P(all zero) ~ 0.
__global__ void k_detect(const void* labels, const void* ncls, int N) {
    __shared__ int ok;
    if (threadIdx.x == 0) ok = 1;
    __syncthreads();
    const int* w = (const int*)labels;
    int half = N / 2;
    int samples = half < 2048 ? half : 2048;
    int stride = samples > 0 ? half / samples : 1;
    int bad = 0;
    for (int s = threadIdx.x; s < samples; s += blockDim.x) {
        int i = s * stride;
        if (w[2 * i + 1] != 0) bad = 1;
    }
    if (bad) ok = 0;
    __syncthreads();
    if (threadIdx.x == 0) {
        g_is64 = ok;
        int c = 100;
        if (ncls) c = ((const int*)ncls)[0]; // low 32 bits valid for int32 or LE int64
        if (c < 1 || c > C_MAX) c = 100;
        g_C = c;
    }
}

__global__ void k_hist(const void* labels, int N) {
    __shared__ int h[C_MAX];
    for (int i = threadIdx.x; i < C_MAX; i += blockDim.x) h[i] = 0;
    __syncthreads();
    int is64 = g_is64;
    for (int i = blockIdx.x * blockDim.x + threadIdx.x; i < N; i += gridDim.x * blockDim.x) {
        int l = get_label(labels, i, is64);
        atomicAdd(&h[l], 1);
    }
    __syncthreads();
    for (int i = threadIdx.x; i < C_MAX; i += blockDim.x)
        if (h[i]) atomicAdd(&g_counts[i], h[i]);
}

// Parallel exclusive scan over C_MAX=256 counts: one block, Hillis-Steele.
__global__ void k_scan() {
    __shared__ int tmp[C_MAX];
    int t = threadIdx.x;             // blockDim.x == C_MAX
    int v = g_counts[t];
    tmp[t] = v;
    __syncthreads();
    #pragma unroll
    for (int o = 1; o < C_MAX; o <<= 1) {
        int x = (t >= o) ? tmp[t - o] : 0;
        __syncthreads();
        tmp[t] += x;
        __syncthreads();
    }
    int excl = tmp[t] - v;
    g_off[t] = excl;
    g_fill[t] = excl;
    if (t == C_MAX - 1) g_off[C_MAX] = tmp[t];
}

__global__ void k_scatter(const void* labels, int N) {
    __shared__ int base[C_MAX];
    __shared__ int cnt1[C_MAX];
    __shared__ int cnt2[C_MAX];
    for (int i = threadIdx.x; i < C_MAX; i += blockDim.x) { cnt1[i] = 0; cnt2[i] = 0; }
    __syncthreads();
    int is64 = g_is64;
    int i = blockIdx.x * blockDim.x + threadIdx.x;
    int l = -1;
    if (i < N) {
        l = get_label(labels, i, is64);
        atomicAdd(&cnt1[l], 1);
    }
    __syncthreads();
    for (int c = threadIdx.x; c < C_MAX; c += blockDim.x)
        if (cnt1[c]) base[c] = atomicAdd(&g_fill[c], cnt1[c]);
    __syncthreads();
    if (i < N) {
        int r = atomicAdd(&cnt2[l], 1);
        int pos = base[l] + r;
        g_idx[pos] = i;
        g_slab[pos] = l;
    }
}

// Pass A: class sums over class-sorted rows, float4 per thread.
// Register accumulation across a run of same-class rows, flush on change.
__global__ void k_sums(const float4* __restrict__ emb, int N, int D4) {
    int col = blockIdx.y * blockDim.x + threadIdx.x; // float4 column
    if (col >= D4) return;
    int D = D4 * 4;
    int p0 = blockIdx.x * PA_ROWS;
    int p1 = min(p0 + PA_ROWS, N);
    int cur = -1;
    float4 acc = make_float4(0.f, 0.f, 0.f, 0.f);
    for (int p = p0; p < p1; p++) {
        int c = g_slab[p];
        if (c != cur) {
            if (cur >= 0) {
                float* dst = &g_sums[(size_t)cur * D + col * 4];
                atomicAdd(dst + 0, acc.x);
                atomicAdd(dst + 1, acc.y);
                atomicAdd(dst + 2, acc.z);
                atomicAdd(dst + 3, acc.w);
            }
            cur = c;
            acc = make_float4(0.f, 0.f, 0.f, 0.f);
        }
        long long i = g_idx[p];
        float4 v = emb[i * (long long)D4 + col];
        acc.x += v.x; acc.y += v.y; acc.z += v.z; acc.w += v.w;
    }
    if (cur >= 0) {
        float* dst = &g_sums[(size_t)cur * D + col * 4];
        atomicAdd(dst + 0, acc.x);
        atomicAdd(dst + 1, acc.y);
        atomicAdd(dst + 2, acc.z);
        atomicAdd(dst + 3, acc.w);
    }
}

__global__ void k_centroid(int D4) {
    int idx = blockIdx.x * blockDim.x + threadIdx.x;
    int C = g_C;
    if (idx >= C * D4) return;
    int c = idx / D4;
    int cnt = g_counts[c];
    float inv = 1.f / (float)max(cnt, 1);
    float4 v = ((float4*)g_sums)[idx];
    v.x *= inv; v.y *= inv; v.z *= inv; v.w *= inv;
    ((float4*)g_sums)[idx] = v;
}

// Pass B: per-sample squared distance to class centroid. One warp per row.
__global__ void k_dist(const float4* __restrict__ emb, const void* labels, int N, int D4) {
    int w = threadIdx.x >> 5, lane = threadIdx.x & 31;
    int r = blockIdx.x * (blockDim.x >> 5) + w;
    if (r >= N) return;
    int is64 = g_is64;
    int l = get_label(labels, r, is64);
    const float4* e = emb + (size_t)r * D4;
    const float4* c = (const float4*)g_sums + (size_t)l * D4;
    float s = 0.f;
    for (int k = lane; k < D4; k += 32) {
        float4 a = e[k];
        float4 b = c[k];
        float dx = a.x - b.x, dy = a.y - b.y, dz = a.z - b.z, dw = a.w - b.w;
        s = fmaf(dx, dx, s);
        s = fmaf(dy, dy, s);
        s = fmaf(dz, dz, s);
        s = fmaf(dw, dw, s);
    }
    #pragma unroll
    for (int o = 16; o; o >>= 1) s += __shfl_down_sync(0xffffffffu, s, o);
    if (lane == 0) g_d[r] = s;
}

// Per-class unbiased variance of d, accumulated into g_loss; count present classes.
__global__ void k_classvar() {
    int c = blockIdx.x;
    if (c >= g_C) return;
    int cnt = g_counts[c];
    if (cnt == 0) return;
    if (threadIdx.x == 0) atomicAdd(&g_npres, 1);
    if (cnt < 2) return;
    int o = g_off[c];
    __shared__ float sh_mean;
    float s = 0.f;
    for (int p = o + threadIdx.x; p < o + cnt; p += blockDim.x) s += g_d[g_idx[p]];
    s = blockReduceSum(s);
    if (threadIdx.x == 0) sh_mean = s / (float)cnt;
    __syncthreads();
    float mean = sh_mean;
    float v = 0.f;
    for (int p = o + threadIdx.x; p < o + cnt; p += blockDim.x) {
        float dv = g_d[g_idx[p]] - mean;
        v = fmaf(dv, dv, v);
    }
    v = blockReduceSum(v);
    if (threadIdx.x == 0) atomicAdd(&g_loss, v / (float)(cnt - 1));
}

__global__ void k_final(float* out) {
    float np = (float)max(g_npres, 1);
    out[0] = BETA * g_loss / np;
}

// -------- launch --------
extern "C" void kernel_launch(void* const* d_in, const int* in_sizes, int n_in,
                              void* d_out, int out_size) {
    const float* emb = (const float*)d_in[0];
    const void*  lab = d_in[1];
    const void*  ncl = (n_in >= 3) ? d_in[2] : nullptr;
    float* out = (float*)d_out;

    int N = in_sizes[1];
    int D = in_sizes[0] / N;
    int D4 = D / 4;                       // D is a multiple of 4 for this problem
    int total4 = C_MAX * D4;

    k_zero<<<(total4 + 255) / 256, 256>>>(total4);
    k_detect<<<1, 256>>>(lab, ncl, N);

    int hist_blocks = min(128, (N + 255) / 256);
    k_hist<<<hist_blocks, 256>>>(lab, N);
    k_scan<<<1, C_MAX>>>();
    k_scatter<<<(N + 255) / 256, 256>>>(lab, N);

    dim3 gA((N + PA_ROWS - 1) / PA_ROWS, (D4 + 255) / 256);
    k_sums<<<gA, 256>>>((const float4*)emb, N, D4);
    k_centroid<<<(C_MAX * D4 + 255) / 256, 256>>>(D4);

    int wpb = 8; // warps per block
    k_dist<<<(N + wpb - 1) / wpb, wpb * 32>>>((const float4*)emb, lab, N, D4);
    k_classvar<<<C_MAX, 256>>>();
    k_final<<<1, 1>>>(out);
}